// round 9
// baseline (speedup 1.0000x reference)
#include <cuda_runtime.h>
#include <cuda_fp16.h>
#include <cstdint>

#define NCHAN 64
#define NPTS  2048
#define DIN   256
#define DOUT  256

// 8 MB scratch: gathered + transposed (n-major) + fp16 weights, Wt[c][n][k]
__device__ __half g_Wt[NCHAN * DIN * DOUT];

// ---------------------------------------------------------------------------
// helpers
// ---------------------------------------------------------------------------
__device__ __forceinline__ void cp16(uint32_t s, const void* g) {
    asm volatile("cp.async.cg.shared.global [%0], [%1], 16;"
                 :: "r"(s), "l"(g) : "memory");
}

__device__ __forceinline__ uint32_t smem_u32(const void* p) {
    uint32_t a;
    asm("{ .reg .u64 t; cvta.to.shared.u64 t, %1; cvt.u32.u64 %0, t; }"
        : "=r"(a) : "l"(p));
    return a;
}

// pack two f32 into f16x2 (lo, hi)
__device__ __forceinline__ uint32_t pack_h2(float lo, float hi) {
    uint32_t r;
    asm("cvt.rn.f16x2.f32 %0, %1, %2;" : "=r"(r) : "f"(hi), "f"(lo));
    return r;
}

__device__ __forceinline__ void mma_f16(float* c, const uint32_t* a, const uint32_t* b) {
    asm volatile(
        "mma.sync.aligned.m16n8k16.row.col.f32.f16.f16.f32 "
        "{%0,%1,%2,%3}, {%4,%5,%6,%7}, {%8,%9}, {%0,%1,%2,%3};"
        : "+f"(c[0]), "+f"(c[1]), "+f"(c[2]), "+f"(c[3])
        : "r"(a[0]), "r"(a[1]), "r"(a[2]), "r"(a[3]), "r"(b[0]), "r"(b[1]));
}

__device__ __forceinline__ void ldm_x4(uint32_t& r0, uint32_t& r1, uint32_t& r2,
                                       uint32_t& r3, uint32_t addr) {
    asm volatile("ldmatrix.sync.aligned.m8n8.x4.shared.b16 {%0,%1,%2,%3}, [%4];"
                 : "=r"(r0), "=r"(r1), "=r"(r2), "=r"(r3) : "r"(addr));
}

// ---------------------------------------------------------------------------
// pre-kernel: gather W[model_idx[c]], transpose to Wt[c][n][k], round to fp16
// ---------------------------------------------------------------------------
__global__ void gather_transpose_kernel(const float* __restrict__ W,
                                        const int* __restrict__ midx) {
    __shared__ float tile[32][33];
    const int c  = blockIdx.z;
    const int m  = midx[c];
    const int kb = blockIdx.x * 32;
    const int nb = blockIdx.y * 32;
    const int tx = threadIdx.x, ty = threadIdx.y;  // (32, 8)

#pragma unroll
    for (int j = 0; j < 32; j += 8)
        tile[ty + j][tx] = W[((size_t)m * DIN + kb + ty + j) * DOUT + nb + tx];
    __syncthreads();
#pragma unroll
    for (int j = 0; j < 32; j += 8) {
        float v = tile[tx][ty + j];
        g_Wt[((size_t)c * DOUT + nb + ty + j) * DIN + kb + tx] = __float2half_rn(v);
    }
}

// ---------------------------------------------------------------------------
// main GEMM: CTA 128x256, 256 threads, warps 2(m) x 4(n), warp 64x64, fp16 MMA
// SMEM: [0..1024) bias
//       [1024..68608)  A tile 128 rows x 264 halves (528B stride)  -- fp16, full K
//       [68608.. )     3 B stages of 256 rows x 72 halves (144B stride)
// ---------------------------------------------------------------------------
static constexpr int BM = 128, BN = 256, BK = 64;
static constexpr int A_STRIDE_B = 528;                 // 264 halves
static constexpr int A_TOT = BM * A_STRIDE_B;          // 67584
static constexpr int B_STRIDE_B = 144;                 // 72 halves
static constexpr int B_STAGE = BN * B_STRIDE_B;        // 36864
static constexpr int A_OFF = 1024;
static constexpr int B_OFF = A_OFF + A_TOT;            // 68608
static constexpr int SMEM_BYTES = B_OFF + 3 * B_STAGE; // 179200

__global__ void __launch_bounds__(256, 1)
adaptive_linear_gemm(const float* __restrict__ x, const float* __restrict__ tvec,
                     const float* __restrict__ Bmat, float* __restrict__ out) {
    extern __shared__ char smem[];
    const uint32_t sb = smem_u32(smem);
    const int tid = threadIdx.x;
    const int c   = blockIdx.y;
    const int m0  = blockIdx.x * BM;

    const int wid = tid >> 5, lane = tid & 31;
    const int wm = wid & 1, wn = wid >> 1;   // warp tile origin (wm*64, wn*64)
    const int g = lane >> 2, t = lane & 3;

    // bias gather into SMEM
    {
        const int bidx = (int)(tvec[c] * 31.0f);
        float* sbias = (float*)smem;
        sbias[tid] = Bmat[bidx * DOUT + tid];
    }

    const float*  xc = x + ((size_t)c * NPTS + m0) * DIN;
    const __half* wc = g_Wt + (size_t)c * DIN * DOUT;

    const uint32_t A_base = sb + A_OFF;
    const uint32_t B_base = sb + B_OFF;

    // --- B stage loader (cp.async): 256 rows x 64 halves ---
    auto load_B = [&](int buf, int ks) {
        const uint32_t b_base = B_base + buf * B_STAGE;
#pragma unroll
        for (int i = 0; i < 8; i++) {
            int ch = tid + i * 256;
            int row = ch >> 3, seg = ch & 7;
            cp16(b_base + (uint32_t)(row * B_STRIDE_B + seg * 16),
                 wc + (size_t)row * DIN + ks * BK + seg * 8);
        }
        asm volatile("cp.async.commit_group;" ::: "memory");
    };

    // --- A chunk LDG (f32) -> convert immediately -> STS later (f16) ---
    const int arow = tid >> 1, apart = tid & 1;   // 2 threads/row, 32 floats each
    uint2 flight[8];                              // pre-packed f16x2 pairs
    auto ldg_A = [&](int ks) {
        const float4* src = (const float4*)(xc + (size_t)arow * DIN + ks * BK + apart * 32);
#pragma unroll
        for (int j = 0; j < 8; j++) {
            float4 v = src[j];
            flight[j].x = pack_h2(v.x, v.y);
            flight[j].y = pack_h2(v.z, v.w);
        }
    };
    auto sts_A = [&](int ks) {
        char* dst = smem + A_OFF + arow * A_STRIDE_B + (ks * BK + apart * 32) * 2;
#pragma unroll
        for (int j = 0; j < 8; j++)
            *(uint2*)(dst + j * 8) = flight[j];
    };

    // --- ldmatrix lane base addresses ---
    const int a_mrow = ((lane >> 3) & 1) * 8 + (lane & 7);
    const int a_koff = ((lane >> 4) & 1) * 8;   // halves
    const uint32_t a_lane = A_base + (uint32_t)((wm * 64 + a_mrow) * A_STRIDE_B + a_koff * 2);
    const int b_nrow = ((lane >> 4) & 1) * 8 + (lane & 7);
    const int b_koff = ((lane >> 3) & 1) * 8;   // halves
    const uint32_t b_lane = (uint32_t)((wn * 64 + b_nrow) * B_STRIDE_B + b_koff * 2);

    float acc[4][8][4];
#pragma unroll
    for (int mi = 0; mi < 4; mi++)
#pragma unroll
        for (int ni = 0; ni < 8; ni++)
#pragma unroll
            for (int j = 0; j < 4; j++) acc[mi][ni][j] = 0.0f;

    uint32_t afr[2][16], bfr[2][16];

    // prologue: B stages 0,1 async; A chunk 0 loaded+stored, chunk 1 in flight
    load_B(0, 0);
    load_B(1, 1);
    ldg_A(0);
    sts_A(0);
    ldg_A(1);

#pragma unroll 1
    for (int ks = 0; ks < 4; ++ks) {
        if (ks < 3) sts_A(ks + 1);   // flight holds chunk ks+1; region disjoint from ks
        if (ks < 3) asm volatile("cp.async.wait_group 1;" ::: "memory");
        else        asm volatile("cp.async.wait_group 0;" ::: "memory");
        __syncthreads();
        if (ks + 2 < 4) { load_B((ks + 2) % 3, ks + 2); ldg_A(ks + 2); }

        const uint32_t a_ks  = a_lane + ks * BK * 2;
        const uint32_t b_buf = B_base + (ks % 3) * B_STAGE + b_lane;

        auto load_frags = [&](int kk, int p) {
#pragma unroll
            for (int mi = 0; mi < 4; mi++)
                ldm_x4(afr[p][mi * 4 + 0], afr[p][mi * 4 + 1],
                       afr[p][mi * 4 + 2], afr[p][mi * 4 + 3],
                       a_ks + (uint32_t)(mi * 16 * A_STRIDE_B + kk * 32));
#pragma unroll
            for (int nip = 0; nip < 4; nip++)
                ldm_x4(bfr[p][nip * 4 + 0], bfr[p][nip * 4 + 1],
                       bfr[p][nip * 4 + 2], bfr[p][nip * 4 + 3],
                       b_buf + (uint32_t)(nip * 16 * B_STRIDE_B + kk * 32));
        };

        load_frags(0, 0);
#pragma unroll
        for (int kk = 0; kk < 4; kk++) {   // four k16 sub-steps per BK=64
            if (kk < 3) load_frags(kk + 1, (kk + 1) & 1);
            const int p = kk & 1;
#pragma unroll
            for (int mi = 0; mi < 4; mi++)
#pragma unroll
                for (int ni = 0; ni < 8; ni++)
                    mma_f16(acc[mi][ni], &afr[p][mi * 4], &bfr[p][ni * 2]);
        }
    }

    // epilogue: accumulators + bias -> gmem (float2 stores)
    {
        const float* sbias = (const float*)smem;
        float* op = out + ((size_t)c * NPTS + m0) * DOUT;
#pragma unroll
        for (int mi = 0; mi < 4; mi++) {
            const int r0 = wm * 64 + mi * 16 + g;
#pragma unroll
            for (int ni = 0; ni < 8; ni++) {
                const int col = wn * 64 + ni * 8 + 2 * t;
                const float b0 = sbias[col], b1 = sbias[col + 1];
                float2 v0 = {acc[mi][ni][0] + b0, acc[mi][ni][1] + b1};
                float2 v1 = {acc[mi][ni][2] + b0, acc[mi][ni][3] + b1};
                *(float2*)(op + (size_t)r0 * DOUT + col) = v0;
                *(float2*)(op + (size_t)(r0 + 8) * DOUT + col) = v1;
            }
        }
    }
}

// ---------------------------------------------------------------------------
// launcher
// ---------------------------------------------------------------------------
extern "C" void kernel_launch(void* const* d_in, const int* in_sizes, int n_in,
                              void* d_out, int out_size) {
    const float* x    = (const float*)d_in[0];
    const float* tvec = (const float*)d_in[1];
    const int*   midx = (const int*)d_in[2];
    const float* W    = (const float*)d_in[3];
    const float* Bm   = (const float*)d_in[4];
    float* out = (float*)d_out;

    cudaFuncSetAttribute(adaptive_linear_gemm,
                         cudaFuncAttributeMaxDynamicSharedMemorySize, SMEM_BYTES);

    gather_transpose_kernel<<<dim3(8, 8, NCHAN), dim3(32, 8)>>>(W, midx);
    adaptive_linear_gemm<<<dim3(NPTS / BM, NCHAN), 256, SMEM_BYTES>>>(x, tvec, Bm, out);
}